// round 6
// baseline (speedup 1.0000x reference)
#include <cuda_runtime.h>
#include <math.h>
#include <stdint.h>

// Shapes (fixed for this problem)
#define kB 4
#define kH 12
#define kS 2048
#define kD 64
#define BSv 64
#define Lv 32
#define NSTEPS 4
#define BH (kB*kH)

typedef unsigned long long ull;

// ---------------- device scratch (module-load allocated) ----------------
// g_lp / g_rp use PERMUTED internal layouts (only their own kernels touch them):
//   g_lp[bh][j][l][p] where p = tx*2 + c  <-> logical k = tx + 16c
//   g_rp[bh][k][j][p] where p = tx*8 + c  <-> logical i = tx + 8c
__device__ float g_lp[(size_t)BH*BSv*Lv*Lv];
__device__ float g_rp[(size_t)BH*Lv*BSv*BSv];
__device__ float g_KR[(size_t)BH*Lv*BSv*kD];      // [bh][k][j][v]  (reused as Y at the end)
__device__ float g_LQ[(size_t)BH*BSv*Lv*kD];      // [bh][j][kk][v]
__device__ float g_r2[BH*Lv*BSv];                 // [bh][k][j]   (logical)
__device__ float g_l2[BH*BSv*Lv];                 // [bh][j][k]   (logical)
__device__ float g_leftF[(size_t)BH*BSv*Lv*Lv];   // final left [bh][j][l][k] (logical)
__device__ float g_eta[kH*2*NSTEPS];              // softplus(step_size)
__device__ float g_asc[kH];                       // softplus(attention_scale)/sqrt(D)

__device__ __forceinline__ float softplusf(float x) {
    return x > 20.f ? x : log1pf(expf(x));
}

__device__ __forceinline__ float rsum16(float v) {
    v += __shfl_xor_sync(0xffffffffu, v, 8);
    v += __shfl_xor_sync(0xffffffffu, v, 4);
    v += __shfl_xor_sync(0xffffffffu, v, 2);
    v += __shfl_xor_sync(0xffffffffu, v, 1);
    return v;
}
__device__ __forceinline__ float rsum8(float v) {
    v += __shfl_xor_sync(0xffffffffu, v, 4);
    v += __shfl_xor_sync(0xffffffffu, v, 2);
    v += __shfl_xor_sync(0xffffffffu, v, 1);
    return v;
}

// ---- packed f32x2 helpers (FFMA2) ----
__device__ __forceinline__ ull pdup(float x) {
    ull r; asm("mov.b64 %0, {%1, %1};" : "=l"(r) : "f"(x)); return r;
}
__device__ __forceinline__ float2 up2(ull v) {
    float2 r; asm("mov.b64 {%0, %1}, %2;" : "=f"(r.x), "=f"(r.y) : "l"(v)); return r;
}
__device__ __forceinline__ void fma2(ull &d, ull a, ull b) {
    asm("fma.rn.f32x2 %0, %1, %2, %0;" : "+l"(d) : "l"(a), "l"(b));
}

__device__ __forceinline__ void cp_async16(uint32_t smem_addr, const void* gptr) {
    asm volatile("cp.async.cg.shared.global [%0], [%1], 16;"
                 :: "r"(smem_addr), "l"(gptr) : "memory");
}
__device__ __forceinline__ void cp_async_commit() {
    asm volatile("cp.async.commit_group;" ::: "memory");
}
__device__ __forceinline__ void cp_async_wait0() {
    asm volatile("cp.async.wait_group 0;" ::: "memory");
}

// ---------------- prep: eta, asc ----------------
__global__ void __launch_bounds__(128) prep_kernel(const float* __restrict__ ascale,
                                                   const float* __restrict__ ssize) {
    int i = threadIdx.x;
    if (i < kH*2*NSTEPS) g_eta[i] = softplusf(ssize[i]);
    if (i < kH) g_asc[i] = softplusf(ascale[i]) * 0.125f;   // 1/sqrt(64)
}

// ---------------- step-0 KR: right0 == 1/64 -> KR0 = colmean of K ----------------
__global__ void __launch_bounds__(256) init_kr_kernel(const float* __restrict__ key) {
    int bh = blockIdx.x / Lv;
    int k  = blockIdx.x % Lv;
    const float* Kt = key + ((size_t)bh*kS + (size_t)k*BSv) * kD;
    __shared__ float s_m[kD];
    int tid = threadIdx.x;
    if (tid < kD) {
        float s = 0.f;
        #pragma unroll 8
        for (int i = 0; i < BSv; i++) s += Kt[(size_t)i*kD + tid];
        s_m[tid] = s * (1.0f/64.0f);
    }
    __syncthreads();
    float* KRo = g_KR + ((size_t)(bh*Lv + k) * BSv) * kD;
    #pragma unroll
    for (int it = 0; it < (BSv*kD)/256; it++) {
        int idx = tid + it*256;
        KRo[idx] = s_m[idx & 63];
    }
}

// ---------------- left step: per (bh, j) ----------------
// s_q / s_kr: row-major pitch 68, filled by cp.async. t2l dot-form FFMA2.
// Thread map: tx = tid&15, ty = tid>>4 ; rows l0 = ty*2 ; k lanes {tx, tx+16}.
#define LPITCH 68
template<bool INIT, bool LAST>
__global__ void __launch_bounds__(256) left_step_kernel(const float* __restrict__ query, int s) {
    __shared__ __align__(16) float s_q [Lv*LPITCH];
    __shared__ __align__(16) float s_kr[Lv*LPITCH];
    __shared__ __align__(16) float s_left[Lv*Lv];
    __shared__ float s_r2c[Lv];

    int bh = blockIdx.x / BSv;
    int j  = blockIdx.x % BSv;
    int h  = bh % kH;
    int tid = threadIdx.x;
    int tx = tid & 15;
    int ty = tid >> 4;
    int l0 = ty*2;

    const size_t lp_base = ((size_t)(bh*BSv + j)) * (Lv*Lv);

    // prefetch lp early (permuted layout: contiguous float2 per thread)
    float2 lpre[2];
    if (!INIT) {
        #pragma unroll
        for (int r = 0; r < 2; r++)
            lpre[r] = *(const float2*)&g_lp[lp_base + (size_t)(l0+r)*Lv + tx*2];
    }

    // cp.async fills: Q rows (l) and KR rows (k) are gmem-contiguous
    {
        uint32_t bQ  = (uint32_t)__cvta_generic_to_shared(s_q);
        uint32_t bKR = (uint32_t)__cvta_generic_to_shared(s_kr);
        const float* Qb  = query + (size_t)bh*kS*kD + (size_t)j*kD;     // + row*4096
        const float* KRb = g_KR  + (size_t)bh*Lv*BSv*kD + (size_t)j*kD; // + row*4096
        #pragma unroll
        for (int it = 0; it < 2; it++) {
            int idx = tid + it*256;        // 0..511
            int row = idx >> 4;            // 0..31
            int m   = idx & 15;
            cp_async16(bQ  + row*(LPITCH*4) + m*16, Qb  + (size_t)row*(BSv*kD) + m*4);
            cp_async16(bKR + row*(LPITCH*4) + m*16, KRb + (size_t)row*(BSv*kD) + m*4);
        }
        cp_async_commit();
    }
    if (!INIT && tid < Lv) s_r2c[tid] = g_r2[(bh*Lv + tid)*BSv + j];
    cp_async_wait0();
    __syncthreads();

    // t2l dot-form: outputs t2l[l0+r][k in {tx, tx+16}], packed over v-pairs
    ull acc00=0ull, acc01=0ull, acc10=0ull, acc11=0ull;
    {
        const float* pA = s_q  + l0*LPITCH;
        const float* pB = s_kr + tx*LPITCH;
        #pragma unroll
        for (int m = 0; m < 16; m++) {
            ulonglong2 a0 = *(const ulonglong2*)(pA + m*4);
            ulonglong2 a1 = *(const ulonglong2*)(pA + LPITCH + m*4);
            ulonglong2 b0 = *(const ulonglong2*)(pB + m*4);
            ulonglong2 b1 = *(const ulonglong2*)(pB + 16*LPITCH + m*4);
            fma2(acc00, a0.x, b0.x); fma2(acc00, a0.y, b0.y);
            fma2(acc01, a0.x, b1.x); fma2(acc01, a0.y, b1.y);
            fma2(acc10, a1.x, b0.x); fma2(acc10, a1.y, b0.y);
            fma2(acc11, a1.x, b1.x); fma2(acc11, a1.y, b1.y);
        }
    }
    float qsc = g_asc[h];
    float t2[2][2];
    { float2 u;
      u = up2(acc00); t2[0][0] = (u.x+u.y)*qsc;
      u = up2(acc01); t2[0][1] = (u.x+u.y)*qsc;
      u = up2(acc10); t2[1][0] = (u.x+u.y)*qsc;
      u = up2(acc11); t2[1][1] = (u.x+u.y)*qsc; }

    // fused dl phase
    float eta = g_eta[h*(2*NSTEPS) + s];
    float r2c0 = INIT ? 0.015625f : s_r2c[tx];
    float r2c1 = INIT ? 0.015625f : s_r2c[tx+16];
    #pragma unroll
    for (int r = 0; r < 2; r++) {
        int lr = l0 + r;
        float2 lp2 = INIT ? make_float2(0.17677669529663687f, 0.17677669529663687f)
                          : lpre[r];
        float ss = rsum16(lp2.x*lp2.x + lp2.y*lp2.y);
        float n  = sqrtf(ss);
        float sc   = n > 0.f ? 1.0f/n : 1.0f;
        float invn = n > 0.f ? 1.0f/n : 0.0f;
        float ls0 = lp2.x*sc, ls1 = lp2.y*sc;
        float le0 = ls0*ls0,  le1 = ls1*ls1;
        s_left[lr*Lv + tx]      = le0;
        s_left[lr*Lv + tx + 16] = le1;
        float dl0 = (r2c0*le0 - t2[r][0]) * 2.f * ls0;
        float dl1 = (r2c1*le1 - t2[r][1]) * 2.f * ls1;
        float dot = rsum16(ls0*dl0 + ls1*dl1);
        dl0 = (dl0 - ls0*dot) * invn;
        dl1 = (dl1 - ls1*dot) * invn;
        float np0 = lp2.x - eta*dl0;
        float np1 = lp2.y - eta*dl1;
        if (!LAST) {
            *(float2*)&g_lp[lp_base + (size_t)lr*Lv + tx*2] = make_float2(np0, np1);
        } else {
            float ss2 = rsum16(np0*np0 + np1*np1);
            float n2  = sqrtf(ss2);
            float sc2 = n2 > 0.f ? 1.0f/n2 : 1.0f;
            float f0 = np0*sc2, f1 = np1*sc2;
            g_leftF[lp_base + (size_t)lr*Lv + tx]      = f0*f0;   // logical layout
            g_leftF[lp_base + (size_t)lr*Lv + tx + 16] = f1*f1;
        }
    }
    __syncthreads();

    // l2[k] = sum_l left^2
    if (tid < Lv) {
        float acc = 0.f;
        #pragma unroll
        for (int l = 0; l < Lv; l++) { float vv = s_left[l*Lv + tid]; acc += vv*vv; }
        g_l2[(size_t)(bh*BSv + j)*Lv + tid] = acc;
    }

    // LQ[kk][v] = sum_l left[l][kk] * q_raw[l][v], then * qsc
    {
        int kk0 = ty*2, v0 = tx*4;
        ull q00=0ull, q01=0ull, q10=0ull, q11=0ull;
        #pragma unroll
        for (int l = 0; l < Lv; l++) {
            float2 a = *(const float2*)&s_left[l*Lv + kk0];
            ulonglong2 b = *(const ulonglong2*)&s_q[l*LPITCH + v0];
            ull ad0 = pdup(a.x), ad1 = pdup(a.y);
            fma2(q00, ad0, b.x); fma2(q01, ad0, b.y);
            fma2(q10, ad1, b.x); fma2(q11, ad1, b.y);
        }
        float* LQo = g_LQ + ((size_t)(bh*BSv + j)) * Lv * kD;
        float2 r00 = up2(q00), r01 = up2(q01), r10 = up2(q10), r11 = up2(q11);
        *(float4*)&LQo[(size_t)kk0*kD + v0] =
            make_float4(r00.x*qsc, r00.y*qsc, r01.x*qsc, r01.y*qsc);
        *(float4*)&LQo[(size_t)(kk0+1)*kD + v0] =
            make_float4(r10.x*qsc, r10.y*qsc, r11.x*qsc, r11.y*qsc);
    }
}

// ---------------- right step: per (bh, k) ----------------
// s_K / s_LQ: row-major pitch 68, cp.async. GEMM1 dot-form over v.
// Thread map: tx = tid&7, tyq = tid>>3 ; rows j0 = tyq*2 ; i lanes tx + 8c.
#define RPITCH 68
#define SMEM_RT_FLOATS (4352*2 + 4096 + 64)

template<bool INIT, int MODE>  // MODE 0: update rp + next KR/r2 ; 1: last step, Y from V
__global__ void __launch_bounds__(256, 4) right_step_kernel(const float* __restrict__ key,
                                                            const float* __restrict__ val,
                                                            int s) {
    extern __shared__ float sm[];
    float* s_K  = sm;              // 64 x pitch68 row-major (logical i)
    float* s_LQ = sm + 4352;       // 64 x pitch68 (logical j); becomes s_RT after GEMM1
    float* s_X  = sm + 8704;       // MODE0: rp staging (64x64); MODE1: V row-major
    float* s_l2 = sm + 12800;      // 64

    int bh = blockIdx.x / Lv;
    int k  = blockIdx.x % Lv;
    int h  = bh % kH;
    int tid = threadIdx.x;
    int tx = tid & 7;
    int tyq = tid >> 3;
    int j0 = tyq*2;

    const size_t rp_base = ((size_t)(bh*Lv + k)) * (BSv*BSv);
    const float* Kt  = key + ((size_t)bh*kS + (size_t)k*BSv) * kD;
    const float* Vt  = val + ((size_t)bh*kS + (size_t)k*BSv) * kD;
    const float* LQb = g_LQ + (size_t)bh*BSv*Lv*kD + (size_t)k*kD;

    // MODE1 prefetches rp into registers early (can't spare smem for both V and rp)
    float4 rpa[2], rpb[2];
    if (!INIT && MODE == 1) {
        #pragma unroll
        for (int r = 0; r < 2; r++) {
            rpa[r] = *(const float4*)&g_rp[rp_base + (size_t)(j0+r)*BSv + tx*8];
            rpb[r] = *(const float4*)&g_rp[rp_base + (size_t)(j0+r)*BSv + tx*8 + 4];
        }
    }

    // cp.async fills
    {
        uint32_t bK  = (uint32_t)__cvta_generic_to_shared(s_K);
        uint32_t bLQ = (uint32_t)__cvta_generic_to_shared(s_LQ);
        uint32_t bX  = (uint32_t)__cvta_generic_to_shared(s_X);
        #pragma unroll
        for (int it = 0; it < 4; it++) {
            int idx = tid + it*256;        // 0..1023
            int row = idx >> 4;
            int m   = idx & 15;
            cp_async16(bK  + row*(RPITCH*4) + m*16, Kt  + (size_t)row*kD + m*4);
            cp_async16(bLQ + row*(RPITCH*4) + m*16, LQb + (size_t)row*(Lv*kD) + m*4);
            if (MODE == 1)
                cp_async16(bX + idx*16, Vt + idx*4);
            else if (!INIT)
                cp_async16(bX + idx*16, &g_rp[rp_base + (size_t)idx*4]);
        }
        cp_async_commit();
    }
    if (tid < BSv) s_l2[tid] = g_l2[(size_t)(bh*BSv + tid)*Lv + k];
    cp_async_wait0();
    __syncthreads();

    // GEMM1 dot-form: t2r[j0+r][tx+8c] packed over v-pairs
    ull acc[2][8] = {};
    {
        const float* pA = s_LQ + j0*RPITCH;
        const float* pB = s_K  + tx*RPITCH;
        #pragma unroll
        for (int m = 0; m < 16; m++) {
            ulonglong2 a0 = *(const ulonglong2*)(pA + m*4);
            ulonglong2 a1 = *(const ulonglong2*)(pA + RPITCH + m*4);
            #pragma unroll
            for (int c = 0; c < 8; c++) {
                ulonglong2 b = *(const ulonglong2*)(pB + c*(8*RPITCH) + m*4);
                fma2(acc[0][c], a0.x, b.x); fma2(acc[0][c], a0.y, b.y);
                fma2(acc[1][c], a1.x, b.x); fma2(acc[1][c], a1.y, b.y);
            }
        }
    }
    float t2[2][8];
    #pragma unroll
    for (int r = 0; r < 2; r++)
        #pragma unroll
        for (int c = 0; c < 8; c++) { float2 u = up2(acc[r][c]); t2[r][c] = u.x + u.y; }
    __syncthreads();   // GEMM1 reads of s_LQ done; s_RT may now overwrite it

    // fused dr phase; rightT[i][j] -> s_RT (= s_LQ region, pitch 68, logical i rows)
    float* s_RT = s_LQ;
    float eta = g_eta[h*(2*NSTEPS) + NSTEPS + s];
    #pragma unroll
    for (int r = 0; r < 2; r++) {
        int jr = j0 + r;
        float p[8];
        if (INIT) {
            #pragma unroll
            for (int c = 0; c < 8; c++) p[c] = 0.125f;
        } else if (MODE == 0) {
            float4 a4 = *(const float4*)&s_X[jr*BSv + tx*8];
            float4 b4 = *(const float4*)&s_X[jr*BSv + tx*8 + 4];
            p[0]=a4.x; p[1]=a4.y; p[2]=a4.z; p[3]=a4.w;
            p[4]=b4.x; p[5]=b4.y; p[6]=b4.z; p[7]=b4.w;
        } else {
            p[0]=rpa[r].x; p[1]=rpa[r].y; p[2]=rpa[r].z; p[3]=rpa[r].w;
            p[4]=rpb[r].x; p[5]=rpb[r].y; p[6]=rpb[r].z; p[7]=rpb[r].w;
        }
        float ss = 0.f;
        #pragma unroll
        for (int c = 0; c < 8; c++) ss += p[c]*p[c];
        ss = rsum8(ss);
        float n  = sqrtf(ss);
        float sc   = n > 0.f ? 1.0f/n : 1.0f;
        float invn = n > 0.f ? 1.0f/n : 0.0f;
        float l2v = s_l2[jr];
        float rs[8], d[8];
        float dot = 0.f;
        #pragma unroll
        for (int c = 0; c < 8; c++) {
            rs[c] = p[c]*sc;
            d[c]  = (l2v*rs[c]*rs[c] - t2[r][c]) * 2.f * rs[c];
            dot += rs[c]*d[c];
        }
        dot = rsum8(dot);
        float np[8];
        float ss2 = 0.f;
        #pragma unroll
        for (int c = 0; c < 8; c++) {
            d[c] = (d[c] - rs[c]*dot) * invn;
            np[c] = p[c] - eta*d[c];
            ss2 += np[c]*np[c];
        }
        if (MODE == 0) {
            *(float4*)&g_rp[rp_base + (size_t)jr*BSv + tx*8]     = make_float4(np[0],np[1],np[2],np[3]);
            *(float4*)&g_rp[rp_base + (size_t)jr*BSv + tx*8 + 4] = make_float4(np[4],np[5],np[6],np[7]);
        }
        ss2 = rsum8(ss2);
        float n2  = sqrtf(ss2);
        float sc2 = n2 > 0.f ? 1.0f/n2 : 1.0f;
        float r2s = 0.f;
        #pragma unroll
        for (int c = 0; c < 8; c++) {
            float rn = np[c]*sc2;
            float rt = rn*rn;
            s_RT[(tx + 8*c)*RPITCH + jr] = rt;
            r2s += rt*rt;
        }
        if (MODE == 0) {
            r2s = rsum8(r2s);
            if (tx == 0) g_r2[(bh*Lv + k)*BSv + jr] = r2s;
        }
    }
    __syncthreads();

    // GEMM2: OUT[j][v] = sum_i rightT[i][j] * Km[i][v]  (Km = s_K MODE0, s_X(V) MODE1)
    float* outp = g_KR + ((size_t)(bh*Lv + k) * BSv) * kD;
    {
        const float* Km = (MODE == 0) ? s_K : s_X;
        const int KMP   = (MODE == 0) ? RPITCH : kD;
        int v0 = tx*8;
        ull a2[2][4] = {};
        #pragma unroll 16
        for (int i = 0; i < BSv; i++) {
            float2 a = *(const float2*)&s_RT[i*RPITCH + j0];
            ulonglong2 b0 = *(const ulonglong2*)&Km[i*KMP + v0];
            ulonglong2 b1 = *(const ulonglong2*)&Km[i*KMP + v0 + 4];
            ull ad0 = pdup(a.x), ad1 = pdup(a.y);
            fma2(a2[0][0], ad0, b0.x); fma2(a2[0][1], ad0, b0.y);
            fma2(a2[0][2], ad0, b1.x); fma2(a2[0][3], ad0, b1.y);
            fma2(a2[1][0], ad1, b0.x); fma2(a2[1][1], ad1, b0.y);
            fma2(a2[1][2], ad1, b1.x); fma2(a2[1][3], ad1, b1.y);
        }
        #pragma unroll
        for (int r = 0; r < 2; r++) {
            float2 o0 = up2(a2[r][0]), o1 = up2(a2[r][1]);
            float2 o2 = up2(a2[r][2]), o3 = up2(a2[r][3]);
            *(float4*)&outp[(size_t)(j0+r)*kD + v0]     = make_float4(o0.x,o0.y,o1.x,o1.y);
            *(float4*)&outp[(size_t)(j0+r)*kD + v0 + 4] = make_float4(o2.x,o2.y,o3.x,o3.y);
        }
    }
}

// ---------------- final Z = left @ Y, scatter to output ----------------
__global__ void __launch_bounds__(256) zout_kernel(float* __restrict__ out) {
    __shared__ __align__(16) float s_left[Lv*Lv];
    __shared__ __align__(16) float s_y[Lv*kD];
    int bh = blockIdx.x / BSv;
    int j  = blockIdx.x % BSv;
    int tid = threadIdx.x;
    size_t lbase = ((size_t)(bh*BSv + j)) * (Lv*Lv);
    #pragma unroll
    for (int it = 0; it < 4; it++) {
        int idx = tid + it*256;
        s_left[idx] = g_leftF[lbase + idx];
    }
    const float* Yb = g_KR + (size_t)bh*Lv*BSv*kD + (size_t)j*kD;
    #pragma unroll
    for (int it = 0; it < 8; it++) {
        int idx = tid + it*256;
        int kk = idx >> 6, v = idx & 63;
        s_y[kk*kD + v] = Yb[(size_t)kk*(BSv*kD) + v];
    }
    __syncthreads();
    int tx = tid & 15, ty = tid >> 4;
    int l00 = ty*2, v0 = tx*4;
    ull a0p0=0ull, a0p1=0ull, a1p0=0ull, a1p1=0ull;
    #pragma unroll
    for (int kk = 0; kk < Lv; kk++) {
        float a0 = s_left[l00*Lv + kk];
        float a1 = s_left[(l00+1)*Lv + kk];
        ulonglong2 b = *(const ulonglong2*)&s_y[kk*kD + v0];
        ull ad0 = pdup(a0), ad1 = pdup(a1);
        fma2(a0p0, ad0, b.x); fma2(a0p1, ad0, b.y);
        fma2(a1p0, ad1, b.x); fma2(a1p1, ad1, b.y);
    }
    float2 r00 = up2(a0p0), r01 = up2(a0p1), r10 = up2(a1p0), r11 = up2(a1p1);
    *(float4*)&out[((size_t)bh*kS + (size_t)l00*BSv + j)*kD + v0] =
        make_float4(r00.x,r00.y,r01.x,r01.y);
    *(float4*)&out[((size_t)bh*kS + (size_t)(l00+1)*BSv + j)*kD + v0] =
        make_float4(r10.x,r10.y,r11.x,r11.y);
}

// ---------------- launch ----------------
extern "C" void kernel_launch(void* const* d_in, const int* in_sizes, int n_in,
                              void* d_out, int out_size) {
    (void)in_sizes; (void)n_in; (void)out_size;
    const float* q      = (const float*)d_in[0];
    const float* key    = (const float*)d_in[1];
    const float* val    = (const float*)d_in[2];
    const float* ascale = (const float*)d_in[3];
    const float* ssz    = (const float*)d_in[4];
    float* out = (float*)d_out;

    const size_t SMEM_R = (size_t)SMEM_RT_FLOATS * sizeof(float);
    cudaFuncSetAttribute(right_step_kernel<true,0>,  cudaFuncAttributeMaxDynamicSharedMemorySize, (int)SMEM_R);
    cudaFuncSetAttribute(right_step_kernel<false,0>, cudaFuncAttributeMaxDynamicSharedMemorySize, (int)SMEM_R);
    cudaFuncSetAttribute(right_step_kernel<false,1>, cudaFuncAttributeMaxDynamicSharedMemorySize, (int)SMEM_R);

    prep_kernel<<<1, 128>>>(ascale, ssz);
    init_kr_kernel<<<BH*Lv, 256>>>(key);

    // s = 0 (INIT: lp/rp are exact constants)
    left_step_kernel<true,false><<<BH*BSv, 256>>>(q, 0);
    right_step_kernel<true,0><<<BH*Lv, 256, SMEM_R>>>(key, val, 0);
    // s = 1..2
    for (int s = 1; s < NSTEPS-1; s++) {
        left_step_kernel<false,false><<<BH*BSv, 256>>>(q, s);
        right_step_kernel<false,0><<<BH*Lv, 256, SMEM_R>>>(key, val, s);
    }
    // s = 3 (LAST: left -> leftF, right -> Y from V)
    left_step_kernel<false,true><<<BH*BSv, 256>>>(q, NSTEPS-1);
    right_step_kernel<false,1><<<BH*Lv, 256, SMEM_R>>>(key, val, NSTEPS-1);

    zout_kernel<<<BH*BSv, 256>>>(out);
}

// round 7
// speedup vs baseline: 1.1337x; 1.1337x over previous
#include <cuda_runtime.h>
#include <math.h>
#include <stdint.h>

// Shapes (fixed for this problem)
#define kB 4
#define kH 12
#define kS 2048
#define kD 64
#define BSv 64
#define Lv 32
#define NSTEPS 4
#define BH (kB*kH)

typedef unsigned long long ull;

// ---------------- device scratch (module-load allocated) ----------------
__device__ float g_lp[(size_t)BH*BSv*Lv*Lv];      // [bh][j][l][k]
__device__ float g_rp[(size_t)BH*Lv*BSv*BSv];     // [bh][k][j][i]
__device__ float g_KR[(size_t)BH*Lv*BSv*kD];      // [bh][k][j][v]  (reused as Y at the end)
__device__ float g_LQ[(size_t)BH*BSv*Lv*kD];      // [bh][j][kk][v]
__device__ float g_r2[BH*Lv*BSv];                 // [bh][k][j]
__device__ float g_l2[BH*BSv*Lv];                 // [bh][j][k]
__device__ float g_leftF[(size_t)BH*BSv*Lv*Lv];   // final left [bh][j][l][k]
__device__ float g_eta[kH*2*NSTEPS];              // softplus(step_size)
__device__ float g_asc[kH];                       // softplus(attention_scale)/sqrt(D)

__device__ __forceinline__ float softplusf(float x) {
    return x > 20.f ? x : log1pf(expf(x));
}

__device__ __forceinline__ float rsum16(float v) {
    v += __shfl_xor_sync(0xffffffffu, v, 8);
    v += __shfl_xor_sync(0xffffffffu, v, 4);
    v += __shfl_xor_sync(0xffffffffu, v, 2);
    v += __shfl_xor_sync(0xffffffffu, v, 1);
    return v;
}
__device__ __forceinline__ float rsum8(float v) {
    v += __shfl_xor_sync(0xffffffffu, v, 4);
    v += __shfl_xor_sync(0xffffffffu, v, 2);
    v += __shfl_xor_sync(0xffffffffu, v, 1);
    return v;
}

// ---- packed f32x2 helpers (FFMA2) ----
__device__ __forceinline__ ull pdup(float x) {
    ull r; asm("mov.b64 %0, {%1, %1};" : "=l"(r) : "f"(x)); return r;
}
__device__ __forceinline__ float2 up2(ull v) {
    float2 r; asm("mov.b64 {%0, %1}, %2;" : "=f"(r.x), "=f"(r.y) : "l"(v)); return r;
}
__device__ __forceinline__ void fma2(ull &d, ull a, ull b) {
    asm("fma.rn.f32x2 %0, %1, %2, %0;" : "+l"(d) : "l"(a), "l"(b));
}

__device__ __forceinline__ void cp_async16(uint32_t smem_addr, const void* gptr) {
    asm volatile("cp.async.cg.shared.global [%0], [%1], 16;"
                 :: "r"(smem_addr), "l"(gptr) : "memory");
}
__device__ __forceinline__ void cp_async_commit() {
    asm volatile("cp.async.commit_group;" ::: "memory");
}
__device__ __forceinline__ void cp_async_wait0() {
    asm volatile("cp.async.wait_group 0;" ::: "memory");
}

// ---------------- prep: eta, asc ----------------
__global__ void __launch_bounds__(128) prep_kernel(const float* __restrict__ ascale,
                                                   const float* __restrict__ ssize) {
    int i = threadIdx.x;
    if (i < kH*2*NSTEPS) g_eta[i] = softplusf(ssize[i]);
    if (i < kH) g_asc[i] = softplusf(ascale[i]) * 0.125f;   // 1/sqrt(64)
}

// ---------------- step-0 KR: right0 == 1/64 -> KR0 = colmean of K ----------------
__global__ void __launch_bounds__(256) init_kr_kernel(const float* __restrict__ key) {
    int bh = blockIdx.x / Lv;
    int k  = blockIdx.x % Lv;
    const float* Kt = key + ((size_t)bh*kS + (size_t)k*BSv) * kD;
    __shared__ float s_m[kD];
    int tid = threadIdx.x;
    if (tid < kD) {
        float s = 0.f;
        #pragma unroll 8
        for (int i = 0; i < BSv; i++) s += Kt[(size_t)i*kD + tid];
        s_m[tid] = s * (1.0f/64.0f);
    }
    __syncthreads();
    float* KRo = g_KR + ((size_t)(bh*Lv + k) * BSv) * kD;
    #pragma unroll
    for (int it = 0; it < (BSv*kD)/256; it++) {
        int idx = tid + it*256;
        KRo[idx] = s_m[idx & 63];
    }
}

// ---------------- left step: per (bh, j), fused, FFMA2 (round-4 proven version) ----------------
// Transposed arrays use XOR swizzle: phys(l, v) = v*32 + (l ^ (((v>>1)&15)<<1))
template<bool INIT, bool LAST>
__global__ void __launch_bounds__(256) left_step_kernel(const float* __restrict__ query, int s) {
    __shared__ float s_left[Lv*Lv];
    __shared__ float s_qT[kD*Lv];
    __shared__ float s_krT[kD*Lv];
    __shared__ float s_q[Lv*kD];
    __shared__ float s_r2c[Lv];

    int bh = blockIdx.x / BSv;
    int j  = blockIdx.x % BSv;
    int h  = bh % kH;
    int tid = threadIdx.x;
    int tx = tid & 15;        // k-tile index
    int ty = tid >> 4;        // l-tile index

    const size_t lp_base = ((size_t)(bh*BSv + j)) * (Lv*Lv);

    // prefetch lp early (hide latency behind fill + GEMM)
    int l0 = ty*2, k0 = tx*2;
    float2 lpre[2];
    if (!INIT) {
        #pragma unroll
        for (int r = 0; r < 2; r++)
            lpre[r] = *(const float2*)&g_lp[lp_base + (size_t)(l0+r)*Lv + k0];
    }

    // load Q (scaled) and KR; build row-major s_q and swizzled transposes
    float qsc = g_asc[h];
    const float* KRb = g_KR + (size_t)bh*Lv*BSv*kD;
    #pragma unroll
    for (int it = 0; it < 2; it++) {
        int idx = tid + it*256;            // 0..511 float4s
        int row = idx >> 4;                // l  0..31
        int m   = idx & 15;
        int vq  = m*4;
        size_t goff = ((size_t)bh*kS + (size_t)row*BSv + j)*kD + vq;
        float4 q4 = *(const float4*)&query[goff];
        q4.x *= qsc; q4.y *= qsc; q4.z *= qsc; q4.w *= qsc;
        *(float4*)&s_q[row*kD + vq] = q4;
        float4 kr4 = *(const float4*)&KRb[((size_t)row*BSv + j)*kD + vq];
        float qv[4] = {q4.x,q4.y,q4.z,q4.w};
        float kv[4] = {kr4.x,kr4.y,kr4.z,kr4.w};
        #pragma unroll
        for (int t = 0; t < 4; t++) {
            int v  = vq + t;
            int sl = row ^ (((v>>1)&15)<<1);
            s_qT [v*Lv + sl] = qv[t];
            s_krT[v*Lv + sl] = kv[t];
        }
    }
    if (!INIT && tid < Lv) s_r2c[tid] = g_r2[(bh*Lv + tid)*BSv + j];
    __syncthreads();

    // t2l[l][k] in registers: rows l0,l0+1 ; k-pair k0,k0+1 (packed f32x2)
    ull accA = 0ull, accB = 0ull;
    #pragma unroll
    for (int v = 0; v < kD; v++) {
        int X = ((v>>1)&15)<<1;
        float2 a = *(const float2*)&s_qT[v*Lv + (l0^X)];
        ull b = *(const ull*)&s_krT[v*Lv + (k0^X)];
        fma2(accA, pdup(a.x), b);
        fma2(accB, pdup(a.y), b);
    }
    float2 t2l0 = up2(accA), t2l1 = up2(accB);

    // fused: normalize lp row, dl, project, update; store left (pre-update)
    float eta = g_eta[h*(2*NSTEPS) + s];
    float r2c0 = INIT ? 0.015625f : s_r2c[k0];
    float r2c1 = INIT ? 0.015625f : s_r2c[k0+1];
    #pragma unroll
    for (int r = 0; r < 2; r++) {
        int lr = l0 + r;
        float2 lp2 = INIT ? make_float2(0.17677669529663687f, 0.17677669529663687f)
                          : lpre[r];
        float ss = rsum16(lp2.x*lp2.x + lp2.y*lp2.y);
        float n  = sqrtf(ss);
        float sc   = n > 0.f ? 1.0f/n : 1.0f;
        float invn = n > 0.f ? 1.0f/n : 0.0f;
        float ls0 = lp2.x*sc, ls1 = lp2.y*sc;
        float le0 = ls0*ls0,  le1 = ls1*ls1;
        *(float2*)&s_left[lr*Lv + k0] = make_float2(le0, le1);
        float t0 = (r==0) ? t2l0.x : t2l1.x;
        float t1 = (r==0) ? t2l0.y : t2l1.y;
        float dl0 = (r2c0*le0 - t0) * 2.f * ls0;
        float dl1 = (r2c1*le1 - t1) * 2.f * ls1;
        float dot = rsum16(ls0*dl0 + ls1*dl1);
        dl0 = (dl0 - ls0*dot) * invn;
        dl1 = (dl1 - ls1*dot) * invn;
        float np0 = lp2.x - eta*dl0;
        float np1 = lp2.y - eta*dl1;
        if (!LAST) {
            *(float2*)&g_lp[lp_base + (size_t)lr*Lv + k0] = make_float2(np0, np1);
        } else {
            float ss2 = rsum16(np0*np0 + np1*np1);
            float n2  = sqrtf(ss2);
            float sc2 = n2 > 0.f ? 1.0f/n2 : 1.0f;
            float f0 = np0*sc2, f1 = np1*sc2;
            *(float2*)&g_leftF[lp_base + (size_t)lr*Lv + k0] = make_float2(f0*f0, f1*f1);
        }
    }
    __syncthreads();

    // l2[k] = sum_l left^2
    if (tid < Lv) {
        float acc = 0.f;
        #pragma unroll
        for (int l = 0; l < Lv; l++) { float vv = s_left[l*Lv + tid]; acc += vv*vv; }
        g_l2[(size_t)(bh*BSv + j)*Lv + tid] = acc;
    }

    // LQ[kk][v] = sum_l left[l][kk]*q[l][v] : kk pair ty*2, v0=tx*4, FFMA2
    {
        int kk0 = ty*2, v0 = tx*4;
        ull a0p0=0ull, a0p1=0ull, a1p0=0ull, a1p1=0ull;
        #pragma unroll
        for (int l = 0; l < Lv; l++) {
            float2 a = *(const float2*)&s_left[l*Lv + kk0];
            ulonglong2 b = *(const ulonglong2*)&s_q[l*kD + v0];
            ull ad0 = pdup(a.x), ad1 = pdup(a.y);
            fma2(a0p0, ad0, b.x); fma2(a0p1, ad0, b.y);
            fma2(a1p0, ad1, b.x); fma2(a1p1, ad1, b.y);
        }
        float* LQo = g_LQ + ((size_t)(bh*BSv + j)) * Lv * kD;
        float2 r00 = up2(a0p0), r01 = up2(a0p1), r10 = up2(a1p0), r11 = up2(a1p1);
        *(float4*)&LQo[(size_t)kk0*kD + v0]     = make_float4(r00.x,r00.y,r01.x,r01.y);
        *(float4*)&LQo[(size_t)(kk0+1)*kD + v0] = make_float4(r10.x,r10.y,r11.x,r11.y);
    }
}

// ---------------- right step: per (bh, k), 128 threads, 4x8 tiles, FFMA2 ----------------
// Transposed arrays use XOR swizzle: phys(i, v) = v*64 + (i ^ (((v>>2)&7)<<2))
#define SMEM_RT_FLOATS (4096*3 + 64)

template<bool INIT, int MODE>  // MODE 0 = update rp + next KR/r2 ; 1 = last step: Y from V
__global__ void __launch_bounds__(128, 4) right_step_kernel(const float* __restrict__ key,
                                                            const float* __restrict__ val,
                                                            int s) {
    extern __shared__ float sm[];
    float* s_KT  = sm;            // swizzled transposed K [v][i']
    float* s_LQT = sm + 4096;     // swizzled transposed LQ [v][j'] ; later swizzled rightT [i][j']
    float* s_Km  = sm + 8192;     // row-major K (MODE0) or V (MODE1), cp.async
    float* s_l2  = sm + 12288;    // 64

    int bh = blockIdx.x / Lv;
    int k  = blockIdx.x % Lv;
    int h  = bh % kH;
    int tid = threadIdx.x;
    int tx = tid & 7;             // i-tile: i0 = tx*8
    int ty = tid >> 3;            // j-tile: j0 = ty*4  (ty 0..15)
    int j0 = ty*4, i0 = tx*8;

    const size_t rp_base = ((size_t)(bh*Lv + k)) * (BSv*BSv);
    const float* Kt  = key + ((size_t)bh*kS + (size_t)k*BSv) * kD;
    const float* Vt  = val + ((size_t)bh*kS + (size_t)k*BSv) * kD;
    const float* LQb = g_LQ + (size_t)bh*BSv*Lv*kD + (size_t)k*kD;

    // prefetch rp into registers at kernel top — latency hidden behind fill + GEMM1
    float4 rpA[4], rpB[4];
    if (!INIT) {
        #pragma unroll
        for (int r = 0; r < 4; r++) {
            rpA[r] = *(const float4*)&g_rp[rp_base + (size_t)(j0+r)*BSv + i0];
            rpB[r] = *(const float4*)&g_rp[rp_base + (size_t)(j0+r)*BSv + i0 + 4];
        }
    }

    // kick off Km (K or V) prefetch — consumed only in GEMM2
    {
        uint32_t sdst = (uint32_t)__cvta_generic_to_shared(s_Km);
        const float4* Gp = (const float4*)(MODE == 0 ? Kt : Vt);
        #pragma unroll
        for (int it = 0; it < 8; it++) {
            int idx = tid + it*128;          // 0..1023 float4s
            cp_async16(sdst + (uint32_t)idx*16, Gp + idx);
        }
        cp_async_commit();
    }

    // load K and LQ, transposed+swizzled
    #pragma unroll
    for (int it = 0; it < 8; it++) {
        int idx = tid + it*128;        // 0..1023 float4s
        int row = idx >> 4;            // i or j: 0..63
        int m   = idx & 15;
        int vq  = m*4;
        int sr  = row ^ ((m & 7) << 2);
        float4 k4 = *(const float4*)&Kt[(size_t)row*kD + vq];
        float4 l4 = *(const float4*)&LQb[(size_t)row*(Lv*kD) + vq];
        s_KT [(vq+0)*BSv + sr] = k4.x; s_KT [(vq+1)*BSv + sr] = k4.y;
        s_KT [(vq+2)*BSv + sr] = k4.z; s_KT [(vq+3)*BSv + sr] = k4.w;
        s_LQT[(vq+0)*BSv + sr] = l4.x; s_LQT[(vq+1)*BSv + sr] = l4.y;
        s_LQT[(vq+2)*BSv + sr] = l4.z; s_LQT[(vq+3)*BSv + sr] = l4.w;
    }
    if (tid < BSv) s_l2[tid] = g_l2[(size_t)(bh*BSv + tid)*Lv + k];
    __syncthreads();

    // GEMM1: t2r[j][i] = sum_v LQ[j][v]*K[i][v]  (4j x 8i tiles, packed f32x2)
    // acc[r][c] packs logical i pair (i0+2c, i0+2c+1) for row j0+r
    ull acc[4][4] = {};
    #pragma unroll
    for (int v = 0; v < kD; v++) {
        int xo = ((v>>2)&7)<<2;
        float4 a4 = *(const float4*)&s_LQT[v*BSv + (j0^xo)];
        int A0 = i0 ^ xo;    // covers logical i0..i0+3 in order
        ulonglong2 b0 = *(const ulonglong2*)&s_KT[v*BSv + A0];
        ulonglong2 b1 = *(const ulonglong2*)&s_KT[v*BSv + (A0 ^ 4)];  // i0+4..i0+7
        ull a0 = pdup(a4.x), a1 = pdup(a4.y), a2 = pdup(a4.z), a3 = pdup(a4.w);
        fma2(acc[0][0], a0, b0.x); fma2(acc[0][1], a0, b0.y);
        fma2(acc[0][2], a0, b1.x); fma2(acc[0][3], a0, b1.y);
        fma2(acc[1][0], a1, b0.x); fma2(acc[1][1], a1, b0.y);
        fma2(acc[1][2], a1, b1.x); fma2(acc[1][3], a1, b1.y);
        fma2(acc[2][0], a2, b0.x); fma2(acc[2][1], a2, b0.y);
        fma2(acc[2][2], a2, b1.x); fma2(acc[2][3], a2, b1.y);
        fma2(acc[3][0], a3, b0.x); fma2(acc[3][1], a3, b0.y);
        fma2(acc[3][2], a3, b1.x); fma2(acc[3][3], a3, b1.y);
    }
    __syncthreads();   // GEMM1 reads of s_LQT done; rightT may overwrite it

    // fused dr phase; rightT[i][j'] -> s_RT (= s_LQT region, swizzled on i)
    float* s_RT = s_LQT;
    float eta = g_eta[h*(2*NSTEPS) + NSTEPS + s];
    #pragma unroll
    for (int r = 0; r < 4; r++) {
        int jr = j0 + r;
        float p[8];
        if (INIT) {
            #pragma unroll
            for (int c = 0; c < 8; c++) p[c] = 0.125f;
        } else {
            p[0]=rpA[r].x; p[1]=rpA[r].y; p[2]=rpA[r].z; p[3]=rpA[r].w;
            p[4]=rpB[r].x; p[5]=rpB[r].y; p[6]=rpB[r].z; p[7]=rpB[r].w;
        }
        float ss = 0.f;
        #pragma unroll
        for (int c = 0; c < 8; c++) ss += p[c]*p[c];
        ss = rsum8(ss);
        float n  = sqrtf(ss);
        float sc   = n > 0.f ? 1.0f/n : 1.0f;
        float invn = n > 0.f ? 1.0f/n : 0.0f;
        float l2v = s_l2[jr];
        float t2[8];
        #pragma unroll
        for (int c = 0; c < 4; c++) {
            float2 u = up2(acc[r][c]);
            t2[2*c] = u.x; t2[2*c+1] = u.y;
        }
        float rs[8], d[8];
        float dot = 0.f;
        #pragma unroll
        for (int c = 0; c < 8; c++) {
            rs[c] = p[c]*sc;
            d[c]  = (l2v*rs[c]*rs[c] - t2[c]) * 2.f * rs[c];
            dot += rs[c]*d[c];
        }
        dot = rsum8(dot);
        float np[8];
        float ss2 = 0.f;
        #pragma unroll
        for (int c = 0; c < 8; c++) {
            d[c]  = (d[c] - rs[c]*dot) * invn;
            np[c] = p[c] - eta*d[c];
            ss2 += np[c]*np[c];
        }
        if (MODE == 0) {
            *(float4*)&g_rp[rp_base + (size_t)jr*BSv + i0]     = make_float4(np[0],np[1],np[2],np[3]);
            *(float4*)&g_rp[rp_base + (size_t)jr*BSv + i0 + 4] = make_float4(np[4],np[5],np[6],np[7]);
        }
        ss2 = rsum8(ss2);
        float n2  = sqrtf(ss2);
        float sc2 = n2 > 0.f ? 1.0f/n2 : 1.0f;
        float r2s = 0.f;
        #pragma unroll
        for (int c = 0; c < 8; c++) {
            float rn = np[c]*sc2;
            float rt = rn*rn;
            int ii = i0 + c;
            int sj = jr ^ (((ii>>2)&7)<<2);
            s_RT[ii*BSv + sj] = rt;
            r2s += rt*rt;
        }
        if (MODE == 0) {
            r2s = rsum8(r2s);
            if (tx == 0) g_r2[(bh*Lv + k)*BSv + jr] = r2s;
        }
    }
    cp_async_wait0();
    __syncthreads();

    // GEMM2: OUT[j][v] = sum_i rightT[i][j] * Km[i][v]  (4j x 8v tiles)
    float* outp = g_KR + ((size_t)(bh*Lv + k) * BSv) * kD;
    {
        int v0 = tx*8;
        ull a2[4][4] = {};
        #pragma unroll 8
        for (int i = 0; i < BSv; i++) {
            int xo = ((i>>2)&7)<<2;
            float4 a4 = *(const float4*)&s_RT[i*BSv + (j0^xo)];
            ulonglong2 b0 = *(const ulonglong2*)&s_Km[i*kD + v0];
            ulonglong2 b1 = *(const ulonglong2*)&s_Km[i*kD + v0 + 4];
            ull a0 = pdup(a4.x), a1 = pdup(a4.y), aa2 = pdup(a4.z), a3 = pdup(a4.w);
            fma2(a2[0][0], a0, b0.x); fma2(a2[0][1], a0, b0.y);
            fma2(a2[0][2], a0, b1.x); fma2(a2[0][3], a0, b1.y);
            fma2(a2[1][0], a1, b0.x); fma2(a2[1][1], a1, b0.y);
            fma2(a2[1][2], a1, b1.x); fma2(a2[1][3], a1, b1.y);
            fma2(a2[2][0], aa2, b0.x); fma2(a2[2][1], aa2, b0.y);
            fma2(a2[2][2], aa2, b1.x); fma2(a2[2][3], aa2, b1.y);
            fma2(a2[3][0], a3, b0.x); fma2(a2[3][1], a3, b0.y);
            fma2(a2[3][2], a3, b1.x); fma2(a2[3][3], a3, b1.y);
        }
        #pragma unroll
        for (int r = 0; r < 4; r++) {
            float2 o0 = up2(a2[r][0]), o1 = up2(a2[r][1]);
            float2 o2 = up2(a2[r][2]), o3 = up2(a2[r][3]);
            *(float4*)&outp[(size_t)(j0+r)*kD + v0]     = make_float4(o0.x,o0.y,o1.x,o1.y);
            *(float4*)&outp[(size_t)(j0+r)*kD + v0 + 4] = make_float4(o2.x,o2.y,o3.x,o3.y);
        }
    }
}

// ---------------- final Z = left @ Y, scatter to output ----------------
__global__ void __launch_bounds__(256) zout_kernel(float* __restrict__ out) {
    __shared__ float s_left[Lv*Lv];
    __shared__ float s_y[Lv*kD];
    int bh = blockIdx.x / BSv;
    int j  = blockIdx.x % BSv;
    int tid = threadIdx.x;
    size_t lbase = ((size_t)(bh*BSv + j)) * (Lv*Lv);
    #pragma unroll
    for (int it = 0; it < 4; it++) {
        int idx = tid + it*256;
        s_left[idx] = g_leftF[lbase + idx];
    }
    const float* Yb = g_KR + (size_t)bh*Lv*BSv*kD + (size_t)j*kD;
    #pragma unroll
    for (int it = 0; it < 8; it++) {
        int idx = tid + it*256;
        int kk = idx >> 6, v = idx & 63;
        s_y[kk*kD + v] = Yb[(size_t)kk*(BSv*kD) + v];
    }
    __syncthreads();
    int tx = tid & 15, ty = tid >> 4;
    int l00 = ty*2, v0 = tx*4;
    ull a0p0=0ull, a0p1=0ull, a1p0=0ull, a1p1=0ull;
    #pragma unroll
    for (int kk = 0; kk < Lv; kk++) {
        float a0 = s_left[l00*Lv + kk];
        float a1 = s_left[(l00+1)*Lv + kk];
        ulonglong2 b = *(const ulonglong2*)&s_y[kk*kD + v0];
        ull ad0 = pdup(a0), ad1 = pdup(a1);
        fma2(a0p0, ad0, b.x); fma2(a0p1, ad0, b.y);
        fma2(a1p0, ad1, b.x); fma2(a1p1, ad1, b.y);
    }
    float2 r00 = up2(a0p0), r01 = up2(a0p1), r10 = up2(a1p0), r11 = up2(a1p1);
    *(float4*)&out[((size_t)bh*kS + (size_t)l00*BSv + j)*kD + v0] =
        make_float4(r00.x,r00.y,r01.x,r01.y);
    *(float4*)&out[((size_t)bh*kS + (size_t)(l00+1)*BSv + j)*kD + v0] =
        make_float4(r10.x,r10.y,r11.x,r11.y);
}

// ---------------- launch ----------------
extern "C" void kernel_launch(void* const* d_in, const int* in_sizes, int n_in,
                              void* d_out, int out_size) {
    (void)in_sizes; (void)n_in; (void)out_size;
    const float* q      = (const float*)d_in[0];
    const float* key    = (const float*)d_in[1];
    const float* val    = (const float*)d_in[2];
    const float* ascale = (const float*)d_in[3];
    const float* ssz    = (const float*)d_in[4];
    float* out = (float*)d_out;

    const size_t SMEM_R = (size_t)SMEM_RT_FLOATS * sizeof(float);
    cudaFuncSetAttribute(right_step_kernel<true,0>,  cudaFuncAttributeMaxDynamicSharedMemorySize, (int)SMEM_R);
    cudaFuncSetAttribute(right_step_kernel<false,0>, cudaFuncAttributeMaxDynamicSharedMemorySize, (int)SMEM_R);
    cudaFuncSetAttribute(right_step_kernel<false,1>, cudaFuncAttributeMaxDynamicSharedMemorySize, (int)SMEM_R);

    prep_kernel<<<1, 128>>>(ascale, ssz);
    init_kr_kernel<<<BH*Lv, 256>>>(key);

    // s = 0 (INIT: lp/rp are exact constants)
    left_step_kernel<true,false><<<BH*BSv, 256>>>(q, 0);
    right_step_kernel<true,0><<<BH*Lv, 128, SMEM_R>>>(key, val, 0);
    // s = 1..2
    for (int s = 1; s < NSTEPS-1; s++) {
        left_step_kernel<false,false><<<BH*BSv, 256>>>(q, s);
        right_step_kernel<false,0><<<BH*Lv, 128, SMEM_R>>>(key, val, s);
    }
    // s = 3 (LAST: left -> leftF, right -> Y from V)
    left_step_kernel<false,true><<<BH*BSv, 256>>>(q, NSTEPS-1);
    right_step_kernel<false,1><<<BH*Lv, 128, SMEM_R>>>(key, val, NSTEPS-1);

    zout_kernel<<<BH*BSv, 256>>>(out);
}